// round 5
// baseline (speedup 1.0000x reference)
#include <cuda_runtime.h>
#include <math_constants.h>

#define BATCH   8
#define NSHAPE  8192
#define NSKEL   2048

#define NB      256
#define XMIN    (-6.0f)
#define INVSTEP 21.3333333f      /* 256 bins over [-6,6] */

#define PTHR    256
#define SCANTHR 128
#define A_S1    128              /* phase-A points, side1 (tile=skel)  */
#define A_S2    256              /* phase-A points, side2 (tile=shape) */
#define S1B     (BATCH * NSHAPE / SCANTHR)   /* 512 */
#define S2B     (BATCH * NSKEL  / SCANTHR)   /* 128 */
#define NBLK    (S1B + S2B)                  /* 640 */

// Sorted point clouds as float4 (x,y,z,|p|^2), per batch, x-bin sorted.
// Rewritten by prep every call; accum/done self-reset => graph-replay safe.
__device__ float4 g_sh4[BATCH][NSHAPE];
__device__ float4 g_sk4[BATCH][NSKEL];
__device__ unsigned int g_cdfSh[BATCH][NB + 1];
__device__ unsigned int g_cdfSk[BATCH][NB + 1];
__device__ float        g_accum;
__device__ unsigned int g_done;

// ---------------------------------------------------------------------------
__device__ __forceinline__ int xbin(float x) {
    int b = (int)floorf((x - XMIN) * INVSTEP);
    return min(max(b, 0), NB - 1);
}
__device__ __forceinline__ float wmaxf(float v) {
#pragma unroll
    for (int o = 16; o > 0; o >>= 1) v = fmaxf(v, __shfl_xor_sync(0xffffffffu, v, o));
    return v;
}
__device__ __forceinline__ float wminf(float v) {
#pragma unroll
    for (int o = 16; o > 0; o >>= 1) v = fminf(v, __shfl_xor_sync(0xffffffffu, v, o));
    return v;
}
__device__ __forceinline__ float block_reduce_sum(float v) {
    __shared__ float warpsum[SCANTHR / 32];
    const int lane = threadIdx.x & 31;
    const int wid  = threadIdx.x >> 5;
#pragma unroll
    for (int o = 16; o > 0; o >>= 1) v += __shfl_down_sync(0xffffffffu, v, o);
    if (lane == 0) warpsum[wid] = v;
    __syncthreads();
    if (wid == 0) {
        v = (lane < (SCANTHR / 32)) ? warpsum[lane] : 0.0f;
#pragma unroll
        for (int o = 16; o > 0; o >>= 1) v += __shfl_down_sync(0xffffffffu, v, o);
    }
    return v;
}

// ---------------------------------------------------------------------------
// Prep: counting sort by x-bin per (array,batch). 16 blocks x 256 threads.
// blocks 0-7: shape[b] (N=8192, stride 6); 8-15: skel[b] (N=2048, stride 3).
// Deterministic: fixed warp->index-chunk ownership, fixed lane ranking.
// ---------------------------------------------------------------------------
__global__ void __launch_bounds__(PTHR) prep_kernel(
    const float* __restrict__ shape, const float* __restrict__ skel)
{
    __shared__ unsigned int sBR[NSHAPE];       // bin<<16 | intra-warp rank
    __shared__ unsigned int wHist[8][NB];
    __shared__ unsigned int sScan[NB];
    __shared__ unsigned int sCdf[NB + 1];

    const int tid  = threadIdx.x;
    const int w    = tid >> 5;
    const int lane = tid & 31;
    const bool isShape = (blockIdx.x < 8);
    const int b      = isShape ? blockIdx.x : blockIdx.x - 8;
    const int N      = isShape ? NSHAPE : NSKEL;
    const int stride = isShape ? 6 : 3;
    const int lgch   = isShape ? 10 : 8;       // log2(N/8)
    const float* src = isShape ? shape + (size_t)b * NSHAPE * 6
                               : skel  + (size_t)b * NSKEL * 3;

    for (int i = tid; i < 8 * NB; i += PTHR) ((unsigned int*)wHist)[i] = 0;
    __syncthreads();

    const int chunk = N >> 3;
    const int base  = w * chunk;
    for (int s = 0; s < chunk / 32; s++) {
        const int i = base + s * 32 + lane;
        const float x = src[i * stride];
        const int bn = xbin(x);
        const unsigned mask  = __match_any_sync(0xffffffffu, bn);
        const unsigned lower = __popc(mask & ((1u << lane) - 1u));
        const unsigned prev  = wHist[w][bn];
        __syncwarp();
        sBR[i] = ((unsigned)bn << 16) | (prev + lower);
        if (lower == 0) wHist[w][bn] = prev + __popc(mask);
        __syncwarp();
    }
    __syncthreads();

    // per-bin across-warp exclusive prefix + bin totals
    if (tid < NB) {
        unsigned run = 0;
#pragma unroll
        for (int ww = 0; ww < 8; ww++) {
            const unsigned c = wHist[ww][tid];
            wHist[ww][tid] = run;
            run += c;
        }
        sScan[tid] = run;
    }
    __syncthreads();
    // inclusive scan over 256 bin totals (Hillis-Steele)
    for (int off = 1; off < NB; off <<= 1) {
        unsigned v = 0;
        if (tid < NB && tid >= off) v = sScan[tid - off];
        __syncthreads();
        if (tid < NB) sScan[tid] += v;
        __syncthreads();
    }
    if (tid < NB) sCdf[tid + 1] = sScan[tid];
    if (tid == 0) sCdf[0] = 0;
    __syncthreads();

    // scatter into sorted float4 (x,y,z,|p|^2)
    float4* dst = isShape ? g_sh4[b] : g_sk4[b];
    for (int i = tid; i < N; i += PTHR) {
        const unsigned br = sBR[i];
        const int bn = br >> 16;
        const unsigned r = sCdf[bn] + wHist[i >> lgch][bn] + (br & 0xffffu);
        const float* p = src + i * stride;
        const float x = p[0], y = p[1], z = p[2];
        dst[r] = make_float4(x, y, z, fmaf(x, x, fmaf(y, y, z * z)));
    }
    unsigned int* gcdf = isShape ? g_cdfSh[b] : g_cdfSk[b];
    if (tid <= NB) gcdf[tid] = sCdf[tid];
}

// ---------------------------------------------------------------------------
// scan a [s,e) range of sorted tile points (s,e multiples of 4), updating
// m = min over (|p|^2 - 2 q.p). Uniform per warp; LDG.128 broadcast.
// ---------------------------------------------------------------------------
__device__ __forceinline__ void scan_range(
    const float4* __restrict__ t4, int s, int e,
    float cx, float cy, float cz, float& m)
{
    for (int j = s; j < e; j += 4) {
        const float4 p0 = t4[j + 0];
        const float4 p1 = t4[j + 1];
        const float4 p2 = t4[j + 2];
        const float4 p3 = t4[j + 3];
        float t0 = fmaf(cx, p0.x, p0.w); t0 = fmaf(cy, p0.y, t0); t0 = fmaf(cz, p0.z, t0);
        float t1 = fmaf(cx, p1.x, p1.w); t1 = fmaf(cy, p1.y, t1); t1 = fmaf(cz, p1.z, t1);
        float t2 = fmaf(cx, p2.x, p2.w); t2 = fmaf(cy, p2.y, t2); t2 = fmaf(cz, p2.z, t2);
        float t3 = fmaf(cx, p3.x, p3.w); t3 = fmaf(cy, p3.y, t3); t3 = fmaf(cz, p3.z, t3);
        m = fminf(m, fminf(fminf(t0, t1), fminf(t2, t3)));
    }
}

// ---------------------------------------------------------------------------
// Scan kernel: one thread = one sorted query; warp windows are lane-uniform.
// Phase A: fixed rank-window centered on warp -> upper bound. Phase B: exact
// bin window from warp-max radius, minus the already-scanned phase-A range.
// Over-scan is safe (min idempotent); pruning is exact (|px-qx| <= d_true).
// ---------------------------------------------------------------------------
__global__ void __launch_bounds__(SCANTHR) scan_kernel(float* __restrict__ out)
{
    __shared__ unsigned int sCdf[NB + 1];

    const int tid = threadIdx.x;
    const int bid = blockIdx.x;
    const bool side1 = (bid < S1B);

    const float4 *Q4, *T4;
    const unsigned int* cdf;
    int NP, A, qidx;
    if (side1) {                       // queries = sorted shape, tile = skel
        const int b = bid >> 6;
        qidx = (bid & 63) * SCANTHR + tid;
        Q4 = g_sh4[b]; T4 = g_sk4[b]; cdf = g_cdfSk[b];
        NP = NSKEL; A = A_S1;
    } else {                           // queries = sorted skel, tile = shape
        const int r = bid - S1B;
        const int b = r >> 4;
        qidx = (r & 15) * SCANTHR + tid;
        Q4 = g_sk4[b]; T4 = g_sh4[b]; cdf = g_cdfSh[b];
        NP = NSHAPE; A = A_S2;
    }

    for (int i = tid; i <= NB; i += SCANTHR) sCdf[i] = cdf[i];

    const float4 q = Q4[qidx];
    const float cx = -2.0f * q.x, cy = -2.0f * q.y, cz = -2.0f * q.z;
    const float qn = q.w;
    __syncthreads();

    // warp-uniform x extents
    const float wxlo = wminf(q.x);
    const float wxhi = wmaxf(q.x);

    // ---- phase A: A points centered on the warp's rank position ----
    const float xm = 0.5f * (wxlo + wxhi);
    int a0 = (int)sCdf[xbin(xm)] - (A >> 1);
    a0 = min(max(a0, 0), NP - A) & ~3;
    const int a1 = a0 + A;

    float m = CUDART_INF_F;
    scan_range(T4, a0, a1, cx, cy, cz, m);

    // ---- radius bound & exact window ----
    const float rad  = sqrtf(fmaxf(qn + m, 0.0f)) * 1.0001f;
    const float rmax = wmaxf(rad);
    const int bLo = xbin(wxlo - rmax);
    const int bHi = xbin(wxhi + rmax);
    const int e0  = (int)sCdf[bLo] & ~3;
    const int e1  = min(((int)sCdf[bHi + 1] + 3) & ~3, NP);

    // ---- phase B: window minus phase-A range (two uniform subloops) ----
    scan_range(T4, min(e0, a0), a0, cx, cy, cz, m);
    scan_range(T4, a1, max(e1, a1), cx, cy, cz, m);

    // ---- finalize ----
    const float s = block_reduce_sum(sqrtf(fmaxf(qn + m, 0.0f)));
    if (tid == 0) {
        atomicAdd(&g_accum, s);
        __threadfence();
        if (atomicAdd(&g_done, 1u) == NBLK - 1) {
            out[0] = atomicExch(&g_accum, 0.0f) * 1.0e-4f;
            g_done = 0;
        }
    }
}

// ---------------------------------------------------------------------------
extern "C" void kernel_launch(void* const* d_in, const int* in_sizes, int n_in,
                              void* d_out, int out_size)
{
    const float* shape = (const float*)d_in[0];  // (8, 8192, 6) fp32
    const float* skel  = (const float*)d_in[1];  // (8, 2048, 3) fp32
    prep_kernel<<<16, PTHR>>>(shape, skel);
    scan_kernel<<<NBLK, SCANTHR>>>((float*)d_out);
}

// round 6
// speedup vs baseline: 7.0092x; 7.0092x over previous
#include <cuda_runtime.h>
#include <math_constants.h>

#define BATCH    8
#define NSHAPE   8192
#define NSKEL    2048
#define SSTRIDE  6
#define TILE     256            // tile points per block
#define NJJ      (TILE / 2)     // 128 packed point-pair entries
#define NQ       4              // queries per thread
#define BLK      256
#define QG       (BLK * NQ)     // 1024 queries per group

#define S1_GROUPS 64            // 8*8192/1024
#define S1_CHUNKS 8             // 2048/256
#define S2_GROUPS 16            // 8*2048/1024
#define S2_CHUNKS 32            // 8192/256
#define S1_BLOCKS (S1_GROUPS * S1_CHUNKS)            // 512
#define NBLOCKS   (S1_BLOCKS + S2_GROUPS * S2_CHUNKS) // 1024
#define NGROUPS   (S1_GROUPS + S2_GROUPS)            // 80
#define NKEYS     (NGROUPS * QG)                     // 81920

// All state zero-initialized at module load and RESTORED to zero by the kernel
// itself each call => single launch, deterministic graph replays, no allocs.
// Min-d2 stored as key = ~bits(d2) (monotone-decreasing since bits(d2) in
// [0,0x7F800000]) => atomicMax(key) == min(d2), and key==0 is the identity.
__device__ unsigned int g_key[NKEYS];
__device__ unsigned int g_gc[NGROUPS];
__device__ unsigned int g_done;
__device__ float        g_accum;

// ---------------------------------------------------------------------------
// packed f32x2 helpers (ptxas never auto-fuses FFMA2 from C++)
// ---------------------------------------------------------------------------
__device__ __forceinline__ unsigned long long pack2(float v) {
    unsigned long long r;
    asm("mov.b64 %0, {%1,%2};" : "=l"(r) : "f"(v), "f"(v));
    return r;
}
__device__ __forceinline__ unsigned long long fma2(unsigned long long a,
                                                   unsigned long long b,
                                                   unsigned long long c) {
    unsigned long long d;
    asm("fma.rn.f32x2 %0, %1, %2, %3;" : "=l"(d) : "l"(a), "l"(b), "l"(c));
    return d;
}
__device__ __forceinline__ void unpack2(unsigned long long v, float& lo, float& hi) {
    asm("mov.b64 {%0,%1}, %2;" : "=f"(lo), "=f"(hi) : "l"(v));
}

__device__ __forceinline__ float block_reduce_sum(float v) {
    __shared__ float warpsum[BLK / 32];
    const int lane = threadIdx.x & 31;
    const int wid  = threadIdx.x >> 5;
#pragma unroll
    for (int o = 16; o > 0; o >>= 1) v += __shfl_down_sync(0xffffffffu, v, o);
    if (lane == 0) warpsum[wid] = v;
    __syncthreads();
    if (wid == 0) {
        v = (lane < (BLK / 32)) ? warpsum[lane] : 0.0f;
#pragma unroll
        for (int o = 16; o > 0; o >>= 1) v += __shfl_down_sync(0xffffffffu, v, o);
    }
    return v;
}

// ---------------------------------------------------------------------------
// Single fused kernel. 1024 uniform blocks of 256 threads (8 warps).
//   blocks [0,512):    side1 — queries = shape pts, tile = 256-pt skel chunk
//   blocks [512,1024): side2 — queries = skel pts,  tile = 256-pt shape chunk
// Tile entry jj packs points j0=2jj, j1=2jj+1:
//   sA[jj]=(x0,x1,y0,y1)  sB[jj]=(z0,z1,n0,n1), n=|p|^2
// Inner loop per jj: 2 LDS.128 + 12 FFMA2 + 8 FMNMX for 8 pairs.
// t_j = n_j - 2 q.p_j ; d2 = max(|q|^2 + min_j t_j, 0); merged via atomicMax.
// ---------------------------------------------------------------------------
__global__ void __launch_bounds__(BLK) chamfer_kernel(
    const float* __restrict__ shape, const float* __restrict__ skel,
    float* __restrict__ out)
{
    __shared__ float4 sA[NJJ];
    __shared__ float4 sB[NJJ];
    __shared__ unsigned int sLast;

    const int tid = threadIdx.x;
    const int bid = blockIdx.x;
    const bool side1 = (bid < S1_BLOCKS);

    int gidx, keybase, need;
    float qxv[NQ], qyv[NQ], qzv[NQ];

    if (side1) {
        const int grp   = bid >> 3;           // 0..63
        const int chunk = bid & 7;            // 0..7
        const int b     = grp >> 3;           // 8 groups per batch
        gidx    = grp;
        keybase = grp * QG;
        need    = S1_CHUNKS;

        // tile: skel[b] points [chunk*256, chunk*256+256)
        const float* tb = skel + ((size_t)b * NSKEL + chunk * TILE) * 3;
        if (tid < NJJ) {
            const int jj = tid;
            const float* s0 = tb + jj * 6;
            const float x0 = s0[0], y0 = s0[1], z0 = s0[2];
            const float x1 = s0[3], y1 = s0[4], z1 = s0[5];
            sA[jj] = make_float4(x0, x1, y0, y1);
            sB[jj] = make_float4(z0, z1,
                                 fmaf(x0, x0, fmaf(y0, y0, z0 * z0)),
                                 fmaf(x1, x1, fmaf(y1, y1, z1 * z1)));
        }
        // queries: shape[b] rows (grp%8)*1024 + tid + 256u
        const float* qb = shape + ((size_t)b * NSHAPE + (grp & 7) * QG + tid) * SSTRIDE;
#pragma unroll
        for (int u = 0; u < NQ; u++) {
            const float* p = qb + u * BLK * SSTRIDE;
            qxv[u] = p[0]; qyv[u] = p[1]; qzv[u] = p[2];
        }
    } else {
        const int r     = bid - S1_BLOCKS;
        const int grp   = r >> 5;             // 0..15
        const int chunk = r & 31;             // 0..31
        const int b     = grp >> 1;           // 2 groups per batch
        gidx    = S1_GROUPS + grp;
        keybase = (S1_GROUPS + grp) * QG;
        need    = S2_CHUNKS;

        // tile: shape[b] points [chunk*256, chunk*256+256) (row stride 6)
        const float* tb = shape + ((size_t)b * NSHAPE + chunk * TILE) * SSTRIDE;
        if (tid < NJJ) {
            const int jj = tid;
            const float* s0 = tb + jj * 2 * SSTRIDE;
            const float x0 = s0[0], y0 = s0[1], z0 = s0[2];
            const float x1 = s0[6], y1 = s0[7], z1 = s0[8];
            sA[jj] = make_float4(x0, x1, y0, y1);
            sB[jj] = make_float4(z0, z1,
                                 fmaf(x0, x0, fmaf(y0, y0, z0 * z0)),
                                 fmaf(x1, x1, fmaf(y1, y1, z1 * z1)));
        }
        // queries: skel[b] rows (grp%2)*1024 + tid + 256u
        const float* qb = skel + ((size_t)b * NSKEL + (grp & 1) * QG + tid) * 3;
#pragma unroll
        for (int u = 0; u < NQ; u++) {
            const float* p = qb + u * BLK * 3;
            qxv[u] = p[0]; qyv[u] = p[1]; qzv[u] = p[2];
        }
    }
    __syncthreads();

    float pp[NQ];
    unsigned long long cx[NQ], cy[NQ], cz[NQ];
#pragma unroll
    for (int u = 0; u < NQ; u++) {
        pp[u] = fmaf(qxv[u], qxv[u], fmaf(qyv[u], qyv[u], qzv[u] * qzv[u]));
        cx[u] = pack2(-2.0f * qxv[u]);
        cy[u] = pack2(-2.0f * qyv[u]);
        cz[u] = pack2(-2.0f * qzv[u]);
    }

    // ---- hot loop: 128 iters, 8 pairs each ----
    const ulonglong2* pA = reinterpret_cast<const ulonglong2*>(sA);
    const ulonglong2* pB = reinterpret_cast<const ulonglong2*>(sB);
    float mlo[NQ], mhi[NQ];
#pragma unroll
    for (int u = 0; u < NQ; u++) { mlo[u] = CUDART_INF_F; mhi[u] = CUDART_INF_F; }

#pragma unroll 8
    for (int jj = 0; jj < NJJ; jj++) {
        const ulonglong2 A = pA[jj];   // (x-pair, y-pair)
        const ulonglong2 B = pB[jj];   // (z-pair, n-pair)
#pragma unroll
        for (int u = 0; u < NQ; u++) {
            unsigned long long t = fma2(cx[u], A.x, B.y);
            t = fma2(cy[u], A.y, t);
            t = fma2(cz[u], B.x, t);
            float lo, hi;
            unpack2(t, lo, hi);
            mlo[u] = fminf(mlo[u], lo);
            mhi[u] = fminf(mhi[u], hi);
        }
    }

    // ---- merge partial minima (key = ~bits, atomicMax, zero-identity) ----
#pragma unroll
    for (int u = 0; u < NQ; u++) {
        const float d2 = fmaxf(pp[u] + fminf(mlo[u], mhi[u]), 0.0f);
        atomicMax(&g_key[keybase + tid + u * BLK],
                  0xFFFFFFFFu ^ __float_as_uint(d2));
    }

    // ---- group completion: last chunk-block finalizes this query group ----
    __threadfence();
    __syncthreads();
    if (tid == 0) sLast = (atomicAdd(&g_gc[gidx], 1u) == (unsigned)(need - 1));
    __syncthreads();
    if (!sLast) return;
    __threadfence();

    float s = 0.0f;
#pragma unroll
    for (int u = 0; u < NQ; u++) {
        // atomicExch: L1-bypassing read + reset-to-zero for the next replay
        const unsigned int key = atomicExch(&g_key[keybase + tid + u * BLK], 0u);
        s += sqrtf(__uint_as_float(0xFFFFFFFFu ^ key));
    }
    s = block_reduce_sum(s);

    if (tid == 0) {
        g_gc[gidx] = 0;                       // reset own counter
        atomicAdd(&g_accum, s);
        __threadfence();
        if (atomicAdd(&g_done, 1u) == NGROUPS - 1) {
            out[0] = atomicExch(&g_accum, 0.0f) * 1.0e-4f;
            g_done = 0;                       // reset for next replay
        }
    }
}

// ---------------------------------------------------------------------------
extern "C" void kernel_launch(void* const* d_in, const int* in_sizes, int n_in,
                              void* d_out, int out_size)
{
    const float* shape = (const float*)d_in[0];  // (8, 8192, 6) fp32
    const float* skel  = (const float*)d_in[1];  // (8, 2048, 3) fp32
    chamfer_kernel<<<NBLOCKS, BLK>>>(shape, skel, (float*)d_out);
}